// round 7
// baseline (speedup 1.0000x reference)
#include <cuda_runtime.h>
#include <cstdint>

// Problem constants (fixed by setup_inputs)
#define B      2
#define NPTS   8192
#define D      256
#define NBINS  32
#define BIN    256
#define TOPK   16
#define NPROJ  16          // n_bins / 2
#define NCHUNK (B * NBINS) // 64 total chunks across batches
#define FIN_BLOCKS 592     // persistent finish blocks (single wave, 4/SM)

__device__ __forceinline__ void pdl_trigger() {
    asm volatile("griddepcontrol.launch_dependents;" ::: "memory");
}
__device__ __forceinline__ void pdl_wait() {
    asm volatile("griddepcontrol.wait;" ::: "memory");
}

// ---------------- scratch (device globals; no allocation allowed) ------------
__device__ int   g_bin_idx[B * NPTS];
__device__ int   g_order  [B * NPTS];
__device__ float g_dm     [NCHUNK * BIN * BIN]; // 16 MB sigmoid(similarity)

// ---------------- K1: projection + argmax over [proj, -proj] ------------------
__global__ __launch_bounds__(256) void k_proj_argmax(
    const float* __restrict__ x, const float* __restrict__ cb) {
    __shared__ float cbs[NPROJ][D];
    int tid = threadIdx.x;
    for (int e = tid; e < D * 32; e += 256) {
        int d = e >> 5, j = e & 31;
        float v = cb[e];
        if (j < NPROJ) cbs[j][d] = v;
    }
    __syncthreads();

    int warp = tid >> 5, lane = tid & 31;
    for (int i = 0; i < 8; i++) {
        int p = blockIdx.x * 64 + warp * 8 + i;
        const float* xr = x + (size_t)p * D;
        float acc[NPROJ];
#pragma unroll
        for (int j = 0; j < NPROJ; j++) acc[j] = 0.f;
#pragma unroll
        for (int k = 0; k < 8; k++) {
            int d = lane + 32 * k;
            float xv = xr[d];
#pragma unroll
            for (int j = 0; j < NPROJ; j++) acc[j] += xv * cbs[j][d];
        }
#pragma unroll
        for (int j = 0; j < NPROJ; j++)
#pragma unroll
            for (int off = 16; off; off >>= 1)
                acc[j] += __shfl_xor_sync(0xFFFFFFFFu, acc[j], off);
        if (lane == 0) {
            float best = acc[0]; int bi = 0;
            for (int jj = 1; jj < 2 * NPROJ; jj++) {
                float v = (jj < NPROJ) ? acc[jj] : -acc[jj - NPROJ];
                if (v > best) { best = v; bi = jj; }
            }
            g_bin_idx[p] = bi;
        }
    }
}

// ---------------- K2: stable counting sort (argsort by bin id) ---------------
__global__ __launch_bounds__(1024) void k_stable_sort() {
    int batch = blockIdx.x;
    const int* bi = g_bin_idx + batch * NPTS;
    int* ord = g_order + batch * NPTS;
    __shared__ int off[NBINS + 1];
    int w = threadIdx.x >> 5, lane = threadIdx.x & 31;

    int total = 0;
    for (int it = 0; it < NPTS / 32; it++) {
        int i = it * 32 + lane;
        unsigned m = __ballot_sync(0xFFFFFFFFu, bi[i] == w);
        total += __popc(m);
    }
    if (lane == 0) off[w + 1] = total;
    __syncthreads();
    if (threadIdx.x == 0) {
        off[0] = 0;
        for (int j = 1; j <= NBINS; j++) off[j] += off[j - 1];
    }
    __syncthreads();

    int pos = off[w];
    for (int it = 0; it < NPTS / 32; it++) {
        int i = it * 32 + lane;
        int b = bi[i];
        unsigned m = __ballot_sync(0xFFFFFFFFu, b == w);
        if (b == w) ord[pos + __popc(m & ((1u << lane) - 1u))] = i;
        pos += __popc(m);
    }
}

// ---------------- K3: symmetric fused gather+GEMM+sigmoid (PDL primary) ------
// Round-2 validated 128x128-tile / 256-thread / 8x8-acc inner loop, applied to
// the 3 upper-triangle 128x128 jobs per 256x256 chunk (UL, UR+mirror, LR).
__global__ __launch_bounds__(256) void k_gemm_sym(const float* __restrict__ x) {
    pdl_trigger(); // let k_finish start zeroing immediately

    __shared__ float As[8][132];
    __shared__ float Bs[8][132];

    int job   = blockIdx.x % 3;   // 0: (0,0)  1: (0,1)+mirror  2: (1,1)
    int chunk = blockIdx.x / 3;
    int b     = chunk >> 5;
    int cbase = (chunk & 31) * BIN;
    int row0  = (job == 2) ? 128 : 0;
    int col0  = (job >= 1) ? 128 : 0;

    int tid = threadIdx.x;
    int halfrow = tid >> 1;   // 0..127
    int q = tid & 1;          // which float4 within 8-wide k window

    int srcA = g_order[b * NPTS + cbase + row0 + halfrow];
    int srcB = g_order[b * NPTS + cbase + col0 + halfrow];
    const float4* pA = (const float4*)(x + ((size_t)b * NPTS + srcA) * D) + q;
    const float4* pB = (const float4*)(x + ((size_t)b * NPTS + srcB) * D) + q;

    int tx = tid & 15, ty = tid >> 4;

    float acc[8][8];
#pragma unroll
    for (int i = 0; i < 8; i++)
#pragma unroll
        for (int j = 0; j < 8; j++) acc[i][j] = 0.f;

    for (int kt = 0; kt < D; kt += 8) {
        float4 va = pA[kt >> 2];
        float4 vb = pB[kt >> 2];
        __syncthreads(); // previous iteration's reads complete before overwrite
        As[4 * q + 0][halfrow] = va.x;
        As[4 * q + 1][halfrow] = va.y;
        As[4 * q + 2][halfrow] = va.z;
        As[4 * q + 3][halfrow] = va.w;
        Bs[4 * q + 0][halfrow] = vb.x;
        Bs[4 * q + 1][halfrow] = vb.y;
        Bs[4 * q + 2][halfrow] = vb.z;
        Bs[4 * q + 3][halfrow] = vb.w;
        __syncthreads();
#pragma unroll
        for (int kk = 0; kk < 8; kk++) {
            float a[8], bb[8];
#pragma unroll
            for (int i = 0; i < 8; i++) a[i] = As[kk][ty * 8 + i];
#pragma unroll
            for (int j = 0; j < 8; j++) bb[j] = Bs[kk][tx * 8 + j];
#pragma unroll
            for (int i = 0; i < 8; i++)
#pragma unroll
                for (int j = 0; j < 8; j++) acc[i][j] += a[i] * bb[j];
        }
    }

    // sigmoid in place
#pragma unroll
    for (int i = 0; i < 8; i++)
#pragma unroll
        for (int j = 0; j < 8; j++)
            acc[i][j] = 1.f / (1.f + expf(-acc[i][j]));

    float* C = g_dm + (size_t)chunk * BIN * BIN;
#pragma unroll
    for (int i = 0; i < 8; i++) {
        int rr = row0 + ty * 8 + i;
        *(float4*)(C + (size_t)rr * BIN + col0 + tx * 8) =
            make_float4(acc[i][0], acc[i][1], acc[i][2], acc[i][3]);
        *(float4*)(C + (size_t)rr * BIN + col0 + tx * 8 + 4) =
            make_float4(acc[i][4], acc[i][5], acc[i][6], acc[i][7]);
    }
    // mirror tile write (transposed), off-diagonal job only; mul commutes bitwise
    if (job == 1) {
#pragma unroll
        for (int j = 0; j < 8; j++) {
            int rr = col0 + tx * 8 + j;
            *(float4*)(C + (size_t)rr * BIN + row0 + ty * 8) =
                make_float4(acc[0][j], acc[1][j], acc[2][j], acc[3][j]);
            *(float4*)(C + (size_t)rr * BIN + row0 + ty * 8 + 4) =
                make_float4(acc[4][j], acc[5][j], acc[6][j], acc[7][j]);
        }
    }
}

// ---------------- K4: persistent finish (PDL secondary) ----------------------
// Phase 1 (overlaps GEMM): zero all assigned output rows.
// Then griddepcontrol.wait (GEMM grid complete) -> phase 2: top-16 + scatter
// for the SAME rows this block zeroed (self-contained; no cross-block deps).
__global__ __launch_bounds__(256) void k_finish(float* __restrict__ out) {
    int bk = blockIdx.x;
    int tid = threadIdx.x;
    const float4 z = make_float4(0.f, 0.f, 0.f, 0.f);

    // ---- phase 1: zero rows bk, bk+FIN_BLOCKS, ... (runs while GEMM runs)
    for (int r = bk; r < B * NPTS; r += FIN_BLOCKS) {
        int b = r >> 13;
        int gsrc = g_order[r]; // sort finished before GEMM launched -> safe
        float4* o4 = (float4*)(out + ((size_t)b * NPTS + gsrc) * NPTS);
#pragma unroll
        for (int j = 0; j < 8; j++) o4[tid + 256 * j] = z;
    }
    __syncthreads();   // all rows of this block zeroed before any scatter
    pdl_wait();        // wait for k_gemm_sym grid completion (g_dm ready)

    // ---- phase 2: top-16 + scatter; warp w handles block rows m == w (mod 8)
    int w = tid >> 5, lane = tid & 31;
    for (int m = w; bk + m * FIN_BLOCKS < B * NPTS; m += 8) {
        int r = bk + m * FIN_BLOCKS;
        const float* dmr = g_dm + (size_t)r * BIN;
        unsigned u[8];
#pragma unroll
        for (int qq = 0; qq < 8; qq++) u[qq] = __float_as_uint(dmr[lane + 32 * qq]);

        int b = r >> 13;
        int jrow = r & (NPTS - 1);
        int chunkoff = b * NPTS + (jrow & ~(BIN - 1));
        int gsrc = g_order[r];
        float* orow = out + ((size_t)b * NPTS + gsrc) * NPTS;

        for (int it = 0; it < TOPK; it++) {
            unsigned best = 0u; int bc = BIN;
#pragma unroll
            for (int qq = 0; qq < 8; qq++) {
                // ascending col within lane + strict '>' keeps min col on ties
                if (u[qq] > best) { best = u[qq]; bc = lane + 32 * qq; }
            }
            unsigned mx = __reduce_max_sync(0xFFFFFFFFu, best);
            int cand = (best == mx) ? bc : (1 << 30);
            int cmin = __reduce_min_sync(0xFFFFFFFFu, cand);
            if ((cmin & 31) == lane) u[cmin >> 5] = 0u; // sigmoid > 0
            if (lane == it) { // spread 16 scattered stores across lanes
                int gdst = g_order[chunkoff + cmin];
                orow[gdst] = __uint_as_float(mx); // unique (gsrc,gdst) -> plain store
            }
        }
    }
}

// ---------------- launch ------------------------------------------------------
extern "C" void kernel_launch(void* const* d_in, const int* in_sizes, int n_in,
                              void* d_out, int out_size) {
    const float* x  = (const float*)d_in[0]; // (2, 8192, 256) f32
    const float* cb = (const float*)d_in[1]; // (256, 32) f32
    float* out = (float*)d_out;              // (2, 8192, 8192) f32

    k_proj_argmax<<<(B * NPTS) / 64, 256>>>(x, cb);
    k_stable_sort<<<B, 1024>>>();
    k_gemm_sym<<<NCHUNK * 3, 256>>>(x);

    // k_finish: programmatic dependent launch -> overlaps k_gemm_sym
    cudaLaunchConfig_t cfg = {};
    cfg.gridDim  = dim3(FIN_BLOCKS, 1, 1);
    cfg.blockDim = dim3(256, 1, 1);
    cfg.dynamicSmemBytes = 0;
    cfg.stream = 0;
    cudaLaunchAttribute attrs[1];
    attrs[0].id = cudaLaunchAttributeProgrammaticStreamSerialization;
    attrs[0].val.programmaticStreamSerializationAllowed = 1;
    cfg.attrs = attrs;
    cfg.numAttrs = 1;
    cudaLaunchKernelEx(&cfg, k_finish, out);
}

// round 8
// speedup vs baseline: 1.2761x; 1.2761x over previous
#include <cuda_runtime.h>
#include <cstdint>

// Problem constants (fixed by setup_inputs)
#define B      2
#define NPTS   8192
#define D      256
#define NBINS  32
#define BIN    256
#define TOPK   16
#define NPROJ  16          // n_bins / 2
#define NCHUNK (B * NBINS) // 64 total chunks across batches
#define KP     16          // k-panel depth for GEMM

// ---- packed f32x2 helpers (Blackwell sm_100+): two independent rn FMAs ------
__device__ __forceinline__ unsigned long long pack2(float lo, float hi) {
    unsigned long long r;
    asm("mov.b64 %0, {%1, %2};"
        : "=l"(r) : "r"(__float_as_uint(lo)), "r"(__float_as_uint(hi)));
    return r;
}
__device__ __forceinline__ void unpack2(unsigned long long v, float& lo, float& hi) {
    unsigned int l, h;
    asm("mov.b64 {%0, %1}, %2;" : "=r"(l), "=r"(h) : "l"(v));
    lo = __uint_as_float(l); hi = __uint_as_float(h);
}
__device__ __forceinline__ void ffma2(unsigned long long& c,
                                      unsigned long long a, unsigned long long b) {
    asm("fma.rn.f32x2 %0, %1, %2, %0;" : "+l"(c) : "l"(a), "l"(b));
}

// ---------------- scratch (device globals; no allocation allowed) ------------
__device__ int   g_bin_idx[B * NPTS];
__device__ int   g_order  [B * NPTS];
__device__ float g_dm     [NCHUNK * BIN * BIN]; // 16 MB sigmoid(similarity)
__device__ int   g_dst    [B * NPTS * TOPK];    // top-k destination indices
__device__ float g_val    [B * NPTS * TOPK];    // top-k values

// upper-triangle 64x64 tile list for a 256x256 chunk (4x4 tile grid)
__constant__ int c_TI[10] = {0,0,0,0,1,1,1,2,2,3};
__constant__ int c_TJ[10] = {0,1,2,3,1,2,3,2,3,3};

// ---------------- K1: projection + argmax over [proj, -proj] ------------------
__global__ __launch_bounds__(256) void k_proj_argmax(
    const float* __restrict__ x, const float* __restrict__ cb) {
    __shared__ float cbs[NPROJ][D];
    int tid = threadIdx.x;
    for (int e = tid; e < D * 32; e += 256) {
        int d = e >> 5, j = e & 31;
        float v = cb[e];
        if (j < NPROJ) cbs[j][d] = v;
    }
    __syncthreads();

    int warp = tid >> 5, lane = tid & 31;
    for (int i = 0; i < 8; i++) {
        int p = blockIdx.x * 64 + warp * 8 + i;
        const float* xr = x + (size_t)p * D;
        float acc[NPROJ];
#pragma unroll
        for (int j = 0; j < NPROJ; j++) acc[j] = 0.f;
#pragma unroll
        for (int k = 0; k < 8; k++) {
            int d = lane + 32 * k;
            float xv = xr[d];
#pragma unroll
            for (int j = 0; j < NPROJ; j++) acc[j] += xv * cbs[j][d];
        }
#pragma unroll
        for (int j = 0; j < NPROJ; j++)
#pragma unroll
            for (int off = 16; off; off >>= 1)
                acc[j] += __shfl_xor_sync(0xFFFFFFFFu, acc[j], off);
        if (lane == 0) {
            float best = acc[0]; int bi = 0;
            for (int jj = 1; jj < 2 * NPROJ; jj++) {
                float v = (jj < NPROJ) ? acc[jj] : -acc[jj - NPROJ];
                if (v > best) { best = v; bi = jj; }
            }
            g_bin_idx[p] = bi;
        }
    }
}

// ---------------- K2: stable counting sort (argsort by bin id) ---------------
__global__ __launch_bounds__(1024) void k_stable_sort() {
    int batch = blockIdx.x;
    const int* bi = g_bin_idx + batch * NPTS;
    int* ord = g_order + batch * NPTS;
    __shared__ int off[NBINS + 1];
    int w = threadIdx.x >> 5, lane = threadIdx.x & 31;

    int total = 0;
    for (int it = 0; it < NPTS / 32; it++) {
        int i = it * 32 + lane;
        unsigned m = __ballot_sync(0xFFFFFFFFu, bi[i] == w);
        total += __popc(m);
    }
    if (lane == 0) off[w + 1] = total;
    __syncthreads();
    if (threadIdx.x == 0) {
        off[0] = 0;
        for (int j = 1; j <= NBINS; j++) off[j] += off[j - 1];
    }
    __syncthreads();

    int pos = off[w];
    for (int it = 0; it < NPTS / 32; it++) {
        int i = it * 32 + lane;
        int b = bi[i];
        unsigned m = __ballot_sync(0xFFFFFFFFu, b == w);
        if (b == w) ord[pos + __popc(m & ((1u << lane) - 1u))] = i;
        pos += __popc(m);
    }
}

// ---------------- K3: symmetric fused gather+GEMM+sigmoid (FFMA2) ------------
// Round-4 structure (640 x 64-thread blocks, 10 upper-tri 64x64 tiles/chunk);
// inner product uses packed fma.rn.f32x2 -> half the fma-pipe issues.
// Each output element keeps one accumulator lane, k ascending: bit-exact.
__global__ __launch_bounds__(64) void k_gemm_sym(const float* __restrict__ x) {
    __shared__ float As[KP][68];
    __shared__ float Bs[KP][68];

    int t     = blockIdx.x % 10;
    int chunk = blockIdx.x / 10;
    int b     = chunk >> 5;
    int cbase = (chunk & 31) * BIN;
    int ti = c_TI[t], tj = c_TJ[t];
    int row0 = ti * 64, col0 = tj * 64;

    int tid = threadIdx.x;
    int q = tid & 3;       // which float4 of the 16-wide k panel
    int rbase = tid >> 2;  // 0..15

    const float* aptr[4];
    const float* bptr[4];
#pragma unroll
    for (int l = 0; l < 4; l++) {
        int r = rbase + 16 * l;
        int sA = g_order[b * NPTS + cbase + row0 + r];
        int sB = g_order[b * NPTS + cbase + col0 + r];
        aptr[l] = x + ((size_t)b * NPTS + sA) * D + q * 4;
        bptr[l] = x + ((size_t)b * NPTS + sB) * D + q * 4;
    }

    int tx = tid & 7, ty = tid >> 3;

    unsigned long long acc2[8][4];
    const unsigned long long z2 = pack2(0.f, 0.f);
#pragma unroll
    for (int i = 0; i < 8; i++)
#pragma unroll
        for (int jp = 0; jp < 4; jp++) acc2[i][jp] = z2;

    float4 va[4], vb[4];
#pragma unroll
    for (int l = 0; l < 4; l++) {
        va[l] = *(const float4*)(aptr[l]);
        vb[l] = *(const float4*)(bptr[l]);
    }

    for (int kt = 0; kt < D; kt += KP) {
        __syncthreads(); // previous compute done reading smem
#pragma unroll
        for (int l = 0; l < 4; l++) {
            int r = rbase + 16 * l;
            As[q * 4 + 0][r] = va[l].x;
            As[q * 4 + 1][r] = va[l].y;
            As[q * 4 + 2][r] = va[l].z;
            As[q * 4 + 3][r] = va[l].w;
            Bs[q * 4 + 0][r] = vb[l].x;
            Bs[q * 4 + 1][r] = vb[l].y;
            Bs[q * 4 + 2][r] = vb[l].z;
            Bs[q * 4 + 3][r] = vb[l].w;
        }
        __syncthreads();
        if (kt + KP < D) { // prefetch next panel while computing
#pragma unroll
            for (int l = 0; l < 4; l++) {
                va[l] = *(const float4*)(aptr[l] + kt + KP);
                vb[l] = *(const float4*)(bptr[l] + kt + KP);
            }
        }
#pragma unroll
        for (int kk = 0; kk < KP; kk++) {
            float4 a0 = *(const float4*)&As[kk][ty * 8];
            float4 a1 = *(const float4*)&As[kk][ty * 8 + 4];
            float4 b0 = *(const float4*)&Bs[kk][tx * 8];
            float4 b1 = *(const float4*)&Bs[kk][tx * 8 + 4];
            float a[8] = {a0.x, a0.y, a0.z, a0.w, a1.x, a1.y, a1.z, a1.w};
            unsigned long long b2[4] = {
                pack2(b0.x, b0.y), pack2(b0.z, b0.w),
                pack2(b1.x, b1.y), pack2(b1.z, b1.w)};
#pragma unroll
            for (int i = 0; i < 8; i++) {
                unsigned long long a2 = pack2(a[i], a[i]);
#pragma unroll
                for (int jp = 0; jp < 4; jp++) ffma2(acc2[i][jp], a2, b2[jp]);
            }
        }
    }

    // unpack + sigmoid
    float acc[8][8];
#pragma unroll
    for (int i = 0; i < 8; i++)
#pragma unroll
        for (int jp = 0; jp < 4; jp++)
            unpack2(acc2[i][jp], acc[i][2 * jp], acc[i][2 * jp + 1]);
#pragma unroll
    for (int i = 0; i < 8; i++)
#pragma unroll
        for (int j = 0; j < 8; j++)
            acc[i][j] = 1.f / (1.f + expf(-acc[i][j]));

    float* C = g_dm + (size_t)chunk * BIN * BIN;
    // normal tile write
#pragma unroll
    for (int i = 0; i < 8; i++) {
        int rr = row0 + ty * 8 + i;
        *(float4*)(C + (size_t)rr * BIN + col0 + tx * 8) =
            make_float4(acc[i][0], acc[i][1], acc[i][2], acc[i][3]);
        *(float4*)(C + (size_t)rr * BIN + col0 + tx * 8 + 4) =
            make_float4(acc[i][4], acc[i][5], acc[i][6], acc[i][7]);
    }
    // mirror tile write (transposed), off-diagonal only; mul commutes bitwise
    if (ti != tj) {
#pragma unroll
        for (int j = 0; j < 8; j++) {
            int rr = col0 + tx * 8 + j;
            *(float4*)(C + (size_t)rr * BIN + row0 + ty * 8) =
                make_float4(acc[0][j], acc[1][j], acc[2][j], acc[3][j]);
            *(float4*)(C + (size_t)rr * BIN + row0 + ty * 8 + 4) =
                make_float4(acc[4][j], acc[5][j], acc[6][j], acc[7][j]);
        }
    }
}

// ---------------- K4: zero output rows + top-16 (no barrier coupling) --------
// one block per output row; warp 0: top-16 then zeroes the row tail,
// warps 1-7 stream-zero the row head. No __syncthreads.
__global__ __launch_bounds__(256) void k_zero_topk(float* __restrict__ out) {
    int row_g = blockIdx.x;              // [0, B*NPTS)
    int lane = threadIdx.x & 31, w = threadIdx.x >> 5;
    int b = row_g >> 13;
    int jrow = row_g & (NPTS - 1);
    int gsrc = g_order[row_g];
    float4* o4 = (float4*)(out + ((size_t)b * NPTS + gsrc) * NPTS);
    float4 z = make_float4(0.f, 0.f, 0.f, 0.f);

    if (w == 0) {
        const float* r = g_dm + (size_t)row_g * BIN;
        unsigned u[8];
#pragma unroll
        for (int q = 0; q < 8; q++) u[q] = __float_as_uint(r[lane + 32 * q]);
        int chunkoff = b * NPTS + (jrow & ~(BIN - 1));
        for (int it = 0; it < TOPK; it++) {
            unsigned best = 0u; int bc = BIN;
#pragma unroll
            for (int q = 0; q < 8; q++) {
                // ascending c within lane + strict '>' keeps min col on ties
                if (u[q] > best) { best = u[q]; bc = lane + 32 * q; }
            }
            unsigned m = __reduce_max_sync(0xFFFFFFFFu, best);
            int cand = (best == m) ? bc : (1 << 30);
            int cmin = __reduce_min_sync(0xFFFFFFFFu, cand);
            if ((cmin & 31) == lane) u[cmin >> 5] = 0u; // sigmoid > 0
            if (lane == it) {
                g_val[row_g * TOPK + it] = __uint_as_float(m);
                g_dst[row_g * TOPK + it] = g_order[chunkoff + cmin];
            }
        }
        // join zeroing: last 256 float4 of the row
#pragma unroll
        for (int j = 0; j < 8; j++) o4[1792 + lane + 32 * j] = z;
    } else {
        // warps 1-7: first 1792 float4 of the row
        int t = threadIdx.x - 32; // 0..223
#pragma unroll
        for (int j = 0; j < 8; j++) o4[t + 224 * j] = z;
    }
}

// ---------------- K5: apply the 262144 top-k stores (after zeroing) ----------
__global__ __launch_bounds__(256) void k_scatter(float* __restrict__ out) {
    int i = blockIdx.x * 256 + threadIdx.x; // [0, B*NPTS*TOPK)
    int row_g = i >> 4;
    int b = row_g >> 13;
    int gsrc = g_order[row_g];
    out[((size_t)b * NPTS + gsrc) * NPTS + g_dst[i]] = g_val[i];
}

// ---------------- launch ------------------------------------------------------
extern "C" void kernel_launch(void* const* d_in, const int* in_sizes, int n_in,
                              void* d_out, int out_size) {
    const float* x  = (const float*)d_in[0]; // (2, 8192, 256) f32
    const float* cb = (const float*)d_in[1]; // (256, 32) f32
    float* out = (float*)d_out;              // (2, 8192, 8192) f32

    k_proj_argmax<<<(B * NPTS) / 64, 256>>>(x, cb);
    k_stable_sort<<<B, 1024>>>();
    k_gemm_sym<<<NCHUNK * 10, 64>>>(x);
    k_zero_topk<<<B * NPTS, 256>>>(out);
    k_scatter<<<(B * NPTS * TOPK) / 256, 256>>>(out);
}